// round 14
// baseline (speedup 1.0000x reference)
#include <cuda_runtime.h>
#include <cstdint>

#define P    1024
#define RDIM 128
#define MDIM 128
#define RPB  2                        // rows per block
#define NBLK (P / RPB)                // 512

__device__ __forceinline__ void cp16(uint32_t dst, const float* src) {
    asm volatile("cp.async.cg.shared.global [%0], [%1], 16;"
                 :: "r"(dst), "l"(src) : "memory");
}

// smem (floats): s_buf 24576 | s_sc 2048 | s_red 32
// After the stream, s_buf is reused: s_nei (2048 ints) at offset 0,
// s_part (2048 floats) at float-offset 2048.
#define STAGES 3
#define SMEM_FLOATS (8 * STAGES * 1024 + 2048 + 32)
#define SMEM_BYTES  (SMEM_FLOATS * 4)   // 106,624 -> 2 CTAs/SM

__global__ __launch_bounds__(256)
void si_fused_kernel(const float* __restrict__ rela,
                     const int*   __restrict__ nei,
                     const float* __restrict__ att_w,
                     const float* __restrict__ att_b,
                     const float* __restrict__ hidden,
                     float*       __restrict__ out)
{
    extern __shared__ float smem[];
    float* s_buf = smem;                               // 24576 floats
    float* s_sc  = smem + 8 * STAGES * 1024;           // 2048 (2 rows)
    float* s_red = s_sc + 2048;                        // 32
    int*   s_nei = (int*)s_buf;                        // alias, post-stream
    float* s_part= s_buf + 2048;                       // alias, post-stream

    const int tid  = threadIdx.x;
    const int lane = tid & 31;
    const int warp = tid >> 5;
    const int i0   = blockIdx.x * RPB;

    // early nei loads into registers (issue now, consumed post-stream)
    const int4 nv0 = reinterpret_cast<const int4*>(nei)[(size_t)i0 * 256 + tid];
    const int4 nv1 = reinterpret_cast<const int4*>(nei)[(size_t)(i0 + 1) * 256 + tid];

    const float4 w4 = reinterpret_cast<const float4*>(att_w)[lane];

    // ================= STREAM: 32 iters x 8 rela-rows =================
    // warp owns j in [warp*128, warp*128+128) for both output rows.
    float* wslab = s_buf + warp * (STAGES * 1024);
    const uint32_t sbase = (uint32_t)__cvta_generic_to_shared(wslab);

    // row r chunk c base pointer
    #define CHUNK_PTR(r, c) (rela + ((size_t)(i0 + (r)) * P + (size_t)warp * 128 \
                             + (size_t)(c) * 8) * RDIM)

    #pragma unroll
    for (int s = 0; s < STAGES; s++) {
        const float* gp = CHUNK_PTR(0, s) + lane * 4;
        const uint32_t dst = sbase + s * 4096 + lane * 16;
        #pragma unroll
        for (int k = 0; k < 8; k++)
            cp16(dst + k * 512, gp + k * RDIM);
        asm volatile("cp.async.commit_group;" ::: "memory");
    }

    int slot = 0;
    #pragma unroll 1
    for (int it = 0; it < 32; it++) {
        asm volatile("cp.async.wait_group %0;" :: "n"(STAGES - 1) : "memory");
        __syncwarp();

        const int row   = it >> 4;
        const int chunk = it & 15;

        const float* sb = wslab + slot * 1024;
        float d[8];
        #pragma unroll
        for (int k = 0; k < 8; k++) {
            const float4 a = *reinterpret_cast<const float4*>(sb + k * 128 + lane * 4);
            d[k] = fmaf(a.x, w4.x,
                   fmaf(a.y, w4.y,
                   fmaf(a.z, w4.z, a.w * w4.w)));
        }

        #pragma unroll
        for (int s2 = 16; s2 >= 4; s2 >>= 1) {
            #pragma unroll
            for (int k = 0; k < 8; k++)
                d[k] += __shfl_xor_sync(0xFFFFFFFFu, d[k], s2);
        }
        const int grp = lane >> 2;
        float v = d[0];
        v = (grp == 1) ? d[1] : v;
        v = (grp == 2) ? d[2] : v;
        v = (grp == 3) ? d[3] : v;
        v = (grp == 4) ? d[4] : v;
        v = (grp == 5) ? d[5] : v;
        v = (grp == 6) ? d[6] : v;
        v = (grp == 7) ? d[7] : v;
        v += __shfl_xor_sync(0xFFFFFFFFu, v, 1);
        v += __shfl_xor_sync(0xFFFFFFFFu, v, 2);
        if ((lane & 3) == 0)
            s_sc[row * 1024 + warp * 128 + chunk * 8 + grp] = v;

        const int it2 = it + STAGES;
        if (it2 < 32) {
            const float* gp = CHUNK_PTR(it2 >> 4, it2 & 15) + lane * 4;
            const uint32_t dst = sbase + slot * 4096 + lane * 16;
            #pragma unroll
            for (int k = 0; k < 8; k++)
                cp16(dst + k * 512, gp + k * RDIM);
        }
        asm volatile("cp.async.commit_group;" ::: "memory");

        if (++slot == STAGES) slot = 0;
    }
    #undef CHUNK_PTR
    __syncthreads();   // stream done; s_buf free for aliases

    // store prefetched nei masks into smem
    reinterpret_cast<int4*>(s_nei)[tid]       = nv0;
    reinterpret_cast<int4*>(s_nei)[256 + tid] = nv1;
    __syncthreads();

    // ================= SOFTMAX x 2 rows =================
    const float b = att_b[0];

    #pragma unroll 1
    for (int r = 0; r < RPB; r++) {
        float* sc = s_sc + r * 1024;
        const int* nrow = s_nei + r * 1024;

        float vals[4];
        unsigned mbits = 0;
        float vmax = -1e30f;
        #pragma unroll
        for (int k = 0; k < 4; k++) {
            const int j = tid + k * 256;
            const bool m = (nrow[j] > 0);
            if (m) mbits |= (1u << k);
            const float v = m ? (sc[j] + b) : -1e-6f;
            vals[k] = v;
            vmax = fmaxf(vmax, v);
        }
        #pragma unroll
        for (int s = 16; s; s >>= 1)
            vmax = fmaxf(vmax, __shfl_xor_sync(0xFFFFFFFFu, vmax, s));
        if (lane == 0) s_red[warp] = vmax;
        __syncthreads();
        {
            float t = s_red[lane & 7];
            #pragma unroll
            for (int s = 4; s; s >>= 1)
                t = fmaxf(t, __shfl_xor_sync(0xFFFFFFFFu, t, s));
            vmax = t;
        }

        float vsum = 0.0f;
        #pragma unroll
        for (int k = 0; k < 4; k++) {
            const float e = __expf(vals[k] - vmax);
            vals[k] = e;
            vsum += e;
        }
        #pragma unroll
        for (int s = 16; s; s >>= 1)
            vsum += __shfl_xor_sync(0xFFFFFFFFu, vsum, s);
        __syncthreads();
        if (lane == 0) s_red[8 + warp] = vsum;
        __syncthreads();
        {
            float t = s_red[8 + (lane & 7)];
            #pragma unroll
            for (int s = 4; s; s >>= 1)
                t += __shfl_xor_sync(0xFFFFFFFFu, t, s);
            vsum = t;
        }
        const float inv = 1.0f / vsum;

        #pragma unroll
        for (int k = 0; k < 4; k++) {
            const int j = tid + k * 256;
            sc[j] = ((mbits >> k) & 1u) ? vals[k] * inv : 0.0f;
        }
        __syncthreads();
    }

    // ================= EPILOGUE GEMV: out[i0+r, :] =================
    // warp (= slice) owns j in [warp*128, warp*128+128); lane owns m4.
    {
        const int m4 = lane;                 // float4 column index 0..31
        const int j0 = warp * 128;
        const float4* h4 = reinterpret_cast<const float4*>(hidden);

        float4 acc0 = {0.f, 0.f, 0.f, 0.f};
        float4 acc1 = {0.f, 0.f, 0.f, 0.f};

        #pragma unroll 1
        for (int j = j0; j < j0 + 128; j += 4) {
            float4 h[4];
            #pragma unroll
            for (int t = 0; t < 4; t++)
                h[t] = h4[(size_t)(j + t) * 32 + m4];

            #pragma unroll
            for (int t = 0; t < 4; t++) {
                const float w0 = s_sc[j + t];
                const float w1 = s_sc[1024 + j + t];
                acc0.x = fmaf(w0, h[t].x, acc0.x);
                acc0.y = fmaf(w0, h[t].y, acc0.y);
                acc0.z = fmaf(w0, h[t].z, acc0.z);
                acc0.w = fmaf(w0, h[t].w, acc0.w);
                acc1.x = fmaf(w1, h[t].x, acc1.x);
                acc1.y = fmaf(w1, h[t].y, acc1.y);
                acc1.z = fmaf(w1, h[t].z, acc1.z);
                acc1.w = fmaf(w1, h[t].w, acc1.w);
            }
        }

        // partials: s_part[row*1024 + warp*128 + m4*4 + c]
        reinterpret_cast<float4*>(s_part)[       warp * 32 + m4] = acc0;
        reinterpret_cast<float4*>(s_part)[256 +  warp * 32 + m4] = acc1;
    }
    __syncthreads();

    // reduce 8 slices per row, write out
    {
        const int row = tid >> 7;       // 0/1
        const int m   = tid & 127;
        float s = 0.0f;
        #pragma unroll
        for (int sl = 0; sl < 8; sl++)
            s += s_part[row * 1024 + sl * 128 + m];
        out[(size_t)(i0 + row) * MDIM + m] = s;
    }
}

extern "C" void kernel_launch(void* const* d_in, const int* in_sizes, int n_in,
                              void* d_out, int out_size)
{
    (void)in_sizes; (void)n_in; (void)out_size;
    const float* hidden = (const float*)d_in[0];   // [1024,128]
    const float* rela   = (const float*)d_in[1];   // [1024,1024,128]
    // d_in[2] = corr_index : unused
    const int*   nei    = (const int*)  d_in[3];   // [1024,1024]
    const float* att_w  = (const float*)d_in[4];   // [128]
    const float* att_b  = (const float*)d_in[5];   // [1]
    float* out = (float*)d_out;                    // [1024,128] f32

    cudaFuncSetAttribute(si_fused_kernel,
                         cudaFuncAttributeMaxDynamicSharedMemorySize,
                         SMEM_BYTES);

    si_fused_kernel<<<NBLK, 256, SMEM_BYTES>>>(
        rela, nei, att_w, att_b, hidden, out);
}

// round 15
// speedup vs baseline: 1.3344x; 1.3344x over previous
#include <cuda_runtime.h>
#include <cstdint>

#define P    1024
#define RDIM 128
#define MDIM 128

#define JSPLIT 8                     // j-splits in GEMM
#define ITILE  32                    // rows per GEMM block
#define NTILES (P / ITILE)           // 32

// Scratch (device globals — allocation-free).
__device__ __align__(16) float g_wbuf[P * P];               // softmax weights, 4 MB
__device__ __align__(16) float g_part[JSPLIT * P * MDIM];   // split-K partials, 4 MB

__device__ __forceinline__ void cp16(uint32_t dst, const float* src) {
    asm volatile("cp.async.cg.shared.global [%0], [%1], 16;"
                 :: "r"(dst), "l"(src) : "memory");
}

// =====================================================================
// Kernel A (R9 winner, unchanged): one block per output row i.
// Per-warp 3-stage cp.async pipeline, then in-block masked softmax.
// =====================================================================
#define STAGES 3
#define A_SMEM_FLOATS (8 * STAGES * 1024 + 1024 + 1024 + 16)
#define A_SMEM_BYTES  (A_SMEM_FLOATS * 4)

__global__ __launch_bounds__(256)
void si_row_kernel(const float* __restrict__ rela,
                   const int*   __restrict__ nei,
                   const float* __restrict__ att_w,
                   const float* __restrict__ att_b,
                   float*       __restrict__ wout)
{
    extern __shared__ float smem[];
    float* s_buf = smem;                               // 8 * STAGES * 1024
    float* s_sc  = smem + 8 * STAGES * 1024;           // 1024
    int*   s_nei = (int*)(s_sc + 1024);                // 1024
    float* s_red = (float*)(s_nei + 1024);             // 16

    const int tid  = threadIdx.x;
    const int lane = tid & 31;
    const int warp = tid >> 5;
    const int i    = blockIdx.x;

    {
        const int4 nv = reinterpret_cast<const int4*>(nei + (size_t)i * P)[tid];
        reinterpret_cast<int4*>(s_nei)[tid] = nv;
    }

    const float4 w4 = reinterpret_cast<const float4*>(att_w)[lane];

    const float* base  = rela + ((size_t)i * P + (size_t)warp * 128) * RDIM;
    float* wslab = s_buf + warp * (STAGES * 1024);
    const uint32_t sbase = (uint32_t)__cvta_generic_to_shared(wslab);

    #pragma unroll
    for (int s = 0; s < STAGES; s++) {
        const float* gp = base + (size_t)s * 8 * RDIM + lane * 4;
        const uint32_t dst = sbase + s * 4096 + lane * 16;
        #pragma unroll
        for (int k = 0; k < 8; k++)
            cp16(dst + k * 512, gp + k * RDIM);
        asm volatile("cp.async.commit_group;" ::: "memory");
    }

    int slot = 0;
    #pragma unroll 1
    for (int it = 0; it < 16; it++) {
        asm volatile("cp.async.wait_group %0;" :: "n"(STAGES - 1) : "memory");
        __syncwarp();

        const float* sb = wslab + slot * 1024;
        float d[8];
        #pragma unroll
        for (int k = 0; k < 8; k++) {
            const float4 a = *reinterpret_cast<const float4*>(sb + k * 128 + lane * 4);
            d[k] = fmaf(a.x, w4.x,
                   fmaf(a.y, w4.y,
                   fmaf(a.z, w4.z, a.w * w4.w)));
        }

        #pragma unroll
        for (int s2 = 16; s2 >= 4; s2 >>= 1) {
            #pragma unroll
            for (int k = 0; k < 8; k++)
                d[k] += __shfl_xor_sync(0xFFFFFFFFu, d[k], s2);
        }
        const int grp = lane >> 2;
        float v = d[0];
        v = (grp == 1) ? d[1] : v;
        v = (grp == 2) ? d[2] : v;
        v = (grp == 3) ? d[3] : v;
        v = (grp == 4) ? d[4] : v;
        v = (grp == 5) ? d[5] : v;
        v = (grp == 6) ? d[6] : v;
        v = (grp == 7) ? d[7] : v;
        v += __shfl_xor_sync(0xFFFFFFFFu, v, 1);
        v += __shfl_xor_sync(0xFFFFFFFFu, v, 2);
        if ((lane & 3) == 0)
            s_sc[warp * 128 + it * 8 + grp] = v;

        if (it + STAGES < 16) {
            const float* gp = base + (size_t)(it + STAGES) * 8 * RDIM + lane * 4;
            const uint32_t dst = sbase + slot * 4096 + lane * 16;
            #pragma unroll
            for (int k = 0; k < 8; k++)
                cp16(dst + k * 512, gp + k * RDIM);
        }
        asm volatile("cp.async.commit_group;" ::: "memory");

        if (++slot == STAGES) slot = 0;
    }
    __syncthreads();

    const float b = att_b[0];

    float vals[4];
    unsigned mbits = 0;
    float vmax = -1e30f;
    #pragma unroll
    for (int k = 0; k < 4; k++) {
        const int j = tid + k * 256;
        const bool m = (s_nei[j] > 0);
        if (m) mbits |= (1u << k);
        const float v = m ? (s_sc[j] + b) : -1e-6f;
        vals[k] = v;
        vmax = fmaxf(vmax, v);
    }
    #pragma unroll
    for (int s = 16; s; s >>= 1)
        vmax = fmaxf(vmax, __shfl_xor_sync(0xFFFFFFFFu, vmax, s));
    if (lane == 0) s_red[warp] = vmax;
    __syncthreads();
    {
        float t = s_red[lane & 7];
        #pragma unroll
        for (int s = 4; s; s >>= 1)
            t = fmaxf(t, __shfl_xor_sync(0xFFFFFFFFu, t, s));
        vmax = t;
    }

    float vsum = 0.0f;
    #pragma unroll
    for (int k = 0; k < 4; k++) {
        const float e = __expf(vals[k] - vmax);
        vals[k] = e;
        vsum += e;
    }
    #pragma unroll
    for (int s = 16; s; s >>= 1)
        vsum += __shfl_xor_sync(0xFFFFFFFFu, vsum, s);
    __syncthreads();
    if (lane == 0) s_red[8 + warp] = vsum;
    __syncthreads();
    {
        float t = s_red[8 + (lane & 7)];
        #pragma unroll
        for (int s = 4; s; s >>= 1)
            t += __shfl_xor_sync(0xFFFFFFFFu, t, s);
        vsum = t;
    }
    const float inv = 1.0f / vsum;

    float* wrow = wout + (size_t)i * P;
    #pragma unroll
    for (int k = 0; k < 4; k++) {
        const int j = tid + k * 256;
        wrow[j] = ((mbits >> k) & 1u) ? vals[k] * inv : 0.0f;
    }
}

// =====================================================================
// Kernel B1: tf32 tensor-core split-K GEMM (R9 design, JSPLIT=8).
// Grid 256 = 32 i-tiles x 8 j-splits; 256 threads (8 warps).
// K-slice 128 per block: 2 chunks of 64, cp.async double-buffered.
// W tile (32 x 128) staged once (tf32); H staged f32, cvt at consume.
// =====================================================================
#define WSTRIDE 132
#define HSTRIDE 136
#define KCHUNK  64
#define NCHUNKS 2
#define B_SMEM ((ITILE * WSTRIDE + 2 * KCHUNK * HSTRIDE) * 4)   // ~86.5 KB

__device__ __forceinline__ uint32_t f2tf32(float f) {
    uint32_t r;
    asm("cvt.rna.tf32.f32 %0, %1;" : "=r"(r) : "f"(f));
    return r;
}

__device__ __forceinline__ void mma_tf32(float d[4],
                                         uint32_t a0, uint32_t a1,
                                         uint32_t a2, uint32_t a3,
                                         uint32_t b0, uint32_t b1)
{
    asm("mma.sync.aligned.m16n8k8.row.col.f32.tf32.tf32.f32 "
        "{%0,%1,%2,%3}, {%4,%5,%6,%7}, {%8,%9}, {%0,%1,%2,%3};"
        : "+f"(d[0]), "+f"(d[1]), "+f"(d[2]), "+f"(d[3])
        : "r"(a0), "r"(a1), "r"(a2), "r"(a3), "r"(b0), "r"(b1));
}

__global__ __launch_bounds__(256)
void si_gemm_tc_kernel(const float* __restrict__ hidden,
                       const float* __restrict__ wsrc,
                       float*       __restrict__ part)
{
    extern __shared__ uint32_t smem_u[];
    uint32_t* s_w = smem_u;                              // [ITILE*WSTRIDE] tf32
    float*    s_h = (float*)(smem_u + ITILE * WSTRIDE);  // [2*KCHUNK*HSTRIDE] f32
    const uint32_t sh_base = (uint32_t)__cvta_generic_to_shared(s_h);

    const int tid  = threadIdx.x;
    const int lane = tid & 31;
    const int warp = tid >> 5;
    const int it   = blockIdx.x >> 3;                // 0..31
    const int js   = blockIdx.x & 7;                 // 0..7
    const int i0   = it * ITILE;
    const int jb   = js * 128;

    // ---- issue H chunk 0 via cp.async (buffer 0) ----
    {
        #pragma unroll
        for (int t = 0; t < 8; t++) {
            const int idx4 = tid + t * 256;          // 0..2047 f4
            const int k    = idx4 >> 5;              // 32 f4 per row
            const int m4   = idx4 & 31;
            cp16(sh_base + (k * HSTRIDE + m4 * 4) * 4,
                 &hidden[(size_t)(jb + k) * MDIM + m4 * 4]);
        }
        asm volatile("cp.async.commit_group;" ::: "memory");
    }

    // ---- stage W tile (32 x 128) tf32 (overlaps chunk-0 latency) ----
    #pragma unroll
    for (int t = 0; t < 4; t++) {
        const int idx4 = tid + t * 256;              // 0..1023 f4
        const int r    = idx4 >> 5;                  // 32 f4 per row
        const int c4   = idx4 & 31;
        const float4 v = *reinterpret_cast<const float4*>(
            &wsrc[(size_t)(i0 + r) * P + jb + c4 * 4]);
        uint4 u;
        u.x = f2tf32(v.x); u.y = f2tf32(v.y);
        u.z = f2tf32(v.z); u.w = f2tf32(v.w);
        *reinterpret_cast<uint4*>(&s_w[r * WSTRIDE + c4 * 4]) = u;
    }

    const int g  = lane >> 2;
    const int tg = lane & 3;
    const int mh = warp >> 2;
    const int nb = (warp & 3) * 32;

    float d[4][4];
    #pragma unroll
    for (int nt = 0; nt < 4; nt++)
        #pragma unroll
        for (int c = 0; c < 4; c++) d[nt][c] = 0.0f;

    #pragma unroll 1
    for (int kci = 0; kci < NCHUNKS; kci++) {
        if (kci + 1 < NCHUNKS) {
            const int kc1 = (kci + 1) * KCHUNK;
            const uint32_t bofs = ((kci + 1) & 1) * (KCHUNK * HSTRIDE) * 4;
            #pragma unroll
            for (int t = 0; t < 8; t++) {
                const int idx4 = tid + t * 256;
                const int k    = idx4 >> 5;
                const int m4   = idx4 & 31;
                cp16(sh_base + bofs + (k * HSTRIDE + m4 * 4) * 4,
                     &hidden[(size_t)(jb + kc1 + k) * MDIM + m4 * 4]);
            }
            asm volatile("cp.async.commit_group;" ::: "memory");
            asm volatile("cp.async.wait_group 1;" ::: "memory");
        } else {
            asm volatile("cp.async.wait_group 0;" ::: "memory");
        }
        __syncthreads();

        const float* sh = s_h + (kci & 1) * (KCHUNK * HSTRIDE);

        #pragma unroll
        for (int ks = 0; ks < 8; ks++) {
            const int kA = kci * KCHUNK + ks * 8;
            const int rowA = mh * 16 + g;
            const uint32_t a0 = s_w[(rowA    ) * WSTRIDE + kA + tg    ];
            const uint32_t a1 = s_w[(rowA + 8) * WSTRIDE + kA + tg    ];
            const uint32_t a2 = s_w[(rowA    ) * WSTRIDE + kA + tg + 4];
            const uint32_t a3 = s_w[(rowA + 8) * WSTRIDE + kA + tg + 4];

            const int kH = ks * 8;
            #pragma unroll
            for (int nt = 0; nt < 4; nt++) {
                const int n = nb + nt * 8 + g;
                const uint32_t b0 = f2tf32(sh[(kH + tg    ) * HSTRIDE + n]);
                const uint32_t b1 = f2tf32(sh[(kH + tg + 4) * HSTRIDE + n]);
                mma_tf32(d[nt], a0, a1, a2, a3, b0, b1);
            }
        }
        __syncthreads();
    }

    // ---- write this block's partial ----
    {
        float* pb = part + (size_t)js * P * MDIM;
        const int r0 = i0 + mh * 16 + g;
        #pragma unroll
        for (int nt = 0; nt < 4; nt++) {
            const int col = nb + nt * 8 + 2 * tg;
            float2 lo; lo.x = d[nt][0]; lo.y = d[nt][1];
            float2 hi; hi.x = d[nt][2]; hi.y = d[nt][3];
            *reinterpret_cast<float2*>(&pb[(size_t)(r0    ) * MDIM + col]) = lo;
            *reinterpret_cast<float2*>(&pb[(size_t)(r0 + 8) * MDIM + col]) = hi;
        }
    }
}

// =====================================================================
// Kernel B2: reduce 8 split-K partials -> out. 131072 floats = 32768 f4.
// =====================================================================
__global__ __launch_bounds__(256)
void si_gemm_reduce_kernel(const float* __restrict__ part,
                           float*       __restrict__ out)
{
    const int e4 = blockIdx.x * 256 + threadIdx.x;   // 0..32767
    const float4* p4 = reinterpret_cast<const float4*>(part);
    float4 s = p4[e4];
    #pragma unroll
    for (int k = 1; k < JSPLIT; k++) {
        const float4 a = p4[(size_t)k * 32768 + e4];
        s.x += a.x; s.y += a.y; s.z += a.z; s.w += a.w;
    }
    reinterpret_cast<float4*>(out)[e4] = s;
}

extern "C" void kernel_launch(void* const* d_in, const int* in_sizes, int n_in,
                              void* d_out, int out_size)
{
    (void)in_sizes; (void)n_in; (void)out_size;
    const float* hidden = (const float*)d_in[0];   // [1024,128]
    const float* rela   = (const float*)d_in[1];   // [1024,1024,128]
    // d_in[2] = corr_index : unused
    const int*   nei    = (const int*)  d_in[3];   // [1024,1024]
    const float* att_w  = (const float*)d_in[4];   // [128]
    const float* att_b  = (const float*)d_in[5];   // [1]
    float* out = (float*)d_out;                    // [1024,128] f32

    float* wbuf;  cudaGetSymbolAddress((void**)&wbuf, g_wbuf);
    float* pbuf;  cudaGetSymbolAddress((void**)&pbuf, g_part);

    cudaFuncSetAttribute(si_row_kernel,
                         cudaFuncAttributeMaxDynamicSharedMemorySize, A_SMEM_BYTES);
    cudaFuncSetAttribute(si_gemm_tc_kernel,
                         cudaFuncAttributeMaxDynamicSharedMemorySize, B_SMEM);

    si_row_kernel<<<P, 256, A_SMEM_BYTES>>>(rela, nei, att_w, att_b, wbuf);
    si_gemm_tc_kernel<<<NTILES * JSPLIT, 256, B_SMEM>>>(hidden, wbuf, pbuf);
    si_gemm_reduce_kernel<<<P * MDIM / 4 / 256, 256>>>(pbuf, out);
}

// round 16
// speedup vs baseline: 1.3645x; 1.0226x over previous
#include <cuda_runtime.h>
#include <cstdint>

#define P    1024
#define RDIM 128
#define MDIM 128

#define JSPLIT 8                     // j-splits in GEMM
#define ITILE  32                    // rows per GEMM block
#define NTILES (P / ITILE)           // 32

// Scratch (device global — allocation-free).
__device__ __align__(16) float g_wbuf[P * P];               // softmax weights, 4 MB

__device__ __forceinline__ void cp16(uint32_t dst, const float* src) {
    asm volatile("cp.async.cg.shared.global [%0], [%1], 16;"
                 :: "r"(dst), "l"(src) : "memory");
}

// =====================================================================
// Kernel A (R15 winner + out zeroing): one block per output row i.
// Per-warp 3-stage cp.async pipeline, then in-block masked softmax.
// Also zeroes out[i, :] so the GEMM can reduce via RED.E.ADD.F32.
// =====================================================================
#define STAGES 3
#define A_SMEM_FLOATS (8 * STAGES * 1024 + 1024 + 1024 + 16)
#define A_SMEM_BYTES  (A_SMEM_FLOATS * 4)

__global__ __launch_bounds__(256)
void si_row_kernel(const float* __restrict__ rela,
                   const int*   __restrict__ nei,
                   const float* __restrict__ att_w,
                   const float* __restrict__ att_b,
                   float*       __restrict__ wout,
                   float*       __restrict__ out)
{
    extern __shared__ float smem[];
    float* s_buf = smem;                               // 8 * STAGES * 1024
    float* s_sc  = smem + 8 * STAGES * 1024;           // 1024
    int*   s_nei = (int*)(s_sc + 1024);                // 1024
    float* s_red = (float*)(s_nei + 1024);             // 16

    const int tid  = threadIdx.x;
    const int lane = tid & 31;
    const int warp = tid >> 5;
    const int i    = blockIdx.x;

    // zero this row of out (B reduces into it with atomics)
    if (tid < 32) {
        const float4 z = {0.f, 0.f, 0.f, 0.f};
        reinterpret_cast<float4*>(out)[(size_t)i * 32 + tid] = z;
    }

    {
        const int4 nv = reinterpret_cast<const int4*>(nei + (size_t)i * P)[tid];
        reinterpret_cast<int4*>(s_nei)[tid] = nv;
    }

    const float4 w4 = reinterpret_cast<const float4*>(att_w)[lane];

    const float* base  = rela + ((size_t)i * P + (size_t)warp * 128) * RDIM;
    float* wslab = s_buf + warp * (STAGES * 1024);
    const uint32_t sbase = (uint32_t)__cvta_generic_to_shared(wslab);

    #pragma unroll
    for (int s = 0; s < STAGES; s++) {
        const float* gp = base + (size_t)s * 8 * RDIM + lane * 4;
        const uint32_t dst = sbase + s * 4096 + lane * 16;
        #pragma unroll
        for (int k = 0; k < 8; k++)
            cp16(dst + k * 512, gp + k * RDIM);
        asm volatile("cp.async.commit_group;" ::: "memory");
    }

    int slot = 0;
    #pragma unroll 1
    for (int it = 0; it < 16; it++) {
        asm volatile("cp.async.wait_group %0;" :: "n"(STAGES - 1) : "memory");
        __syncwarp();

        const float* sb = wslab + slot * 1024;
        float d[8];
        #pragma unroll
        for (int k = 0; k < 8; k++) {
            const float4 a = *reinterpret_cast<const float4*>(sb + k * 128 + lane * 4);
            d[k] = fmaf(a.x, w4.x,
                   fmaf(a.y, w4.y,
                   fmaf(a.z, w4.z, a.w * w4.w)));
        }

        #pragma unroll
        for (int s2 = 16; s2 >= 4; s2 >>= 1) {
            #pragma unroll
            for (int k = 0; k < 8; k++)
                d[k] += __shfl_xor_sync(0xFFFFFFFFu, d[k], s2);
        }
        const int grp = lane >> 2;
        float v = d[0];
        v = (grp == 1) ? d[1] : v;
        v = (grp == 2) ? d[2] : v;
        v = (grp == 3) ? d[3] : v;
        v = (grp == 4) ? d[4] : v;
        v = (grp == 5) ? d[5] : v;
        v = (grp == 6) ? d[6] : v;
        v = (grp == 7) ? d[7] : v;
        v += __shfl_xor_sync(0xFFFFFFFFu, v, 1);
        v += __shfl_xor_sync(0xFFFFFFFFu, v, 2);
        if ((lane & 3) == 0)
            s_sc[warp * 128 + it * 8 + grp] = v;

        if (it + STAGES < 16) {
            const float* gp = base + (size_t)(it + STAGES) * 8 * RDIM + lane * 4;
            const uint32_t dst = sbase + slot * 4096 + lane * 16;
            #pragma unroll
            for (int k = 0; k < 8; k++)
                cp16(dst + k * 512, gp + k * RDIM);
        }
        asm volatile("cp.async.commit_group;" ::: "memory");

        if (++slot == STAGES) slot = 0;
    }
    __syncthreads();

    const float b = att_b[0];

    float vals[4];
    unsigned mbits = 0;
    float vmax = -1e30f;
    #pragma unroll
    for (int k = 0; k < 4; k++) {
        const int j = tid + k * 256;
        const bool m = (s_nei[j] > 0);
        if (m) mbits |= (1u << k);
        const float v = m ? (s_sc[j] + b) : -1e-6f;
        vals[k] = v;
        vmax = fmaxf(vmax, v);
    }
    #pragma unroll
    for (int s = 16; s; s >>= 1)
        vmax = fmaxf(vmax, __shfl_xor_sync(0xFFFFFFFFu, vmax, s));
    if (lane == 0) s_red[warp] = vmax;
    __syncthreads();
    {
        float t = s_red[lane & 7];
        #pragma unroll
        for (int s = 4; s; s >>= 1)
            t = fmaxf(t, __shfl_xor_sync(0xFFFFFFFFu, t, s));
        vmax = t;
    }

    float vsum = 0.0f;
    #pragma unroll
    for (int k = 0; k < 4; k++) {
        const float e = __expf(vals[k] - vmax);
        vals[k] = e;
        vsum += e;
    }
    #pragma unroll
    for (int s = 16; s; s >>= 1)
        vsum += __shfl_xor_sync(0xFFFFFFFFu, vsum, s);
    __syncthreads();
    if (lane == 0) s_red[8 + warp] = vsum;
    __syncthreads();
    {
        float t = s_red[8 + (lane & 7)];
        #pragma unroll
        for (int s = 4; s; s >>= 1)
            t += __shfl_xor_sync(0xFFFFFFFFu, t, s);
        vsum = t;
    }
    const float inv = 1.0f / vsum;

    float* wrow = wout + (size_t)i * P;
    #pragma unroll
    for (int k = 0; k < 4; k++) {
        const int j = tid + k * 256;
        wrow[j] = ((mbits >> k) & 1u) ? vals[k] * inv : 0.0f;
    }
}

// =====================================================================
// Kernel B: tf32 tensor-core split-K GEMM (R15 tiling, JSPLIT=8),
// reducing directly into out via RED.E.ADD.F32 (out pre-zeroed by A).
// Grid 256 = 32 i-tiles x 8 j-splits; 256 threads (8 warps).
// K-slice 128 per block: 2 chunks of 64, cp.async double-buffered.
// =====================================================================
#define WSTRIDE 132
#define HSTRIDE 136
#define KCHUNK  64
#define NCHUNKS 2
#define B_SMEM ((ITILE * WSTRIDE + 2 * KCHUNK * HSTRIDE) * 4)   // ~86.5 KB

__device__ __forceinline__ uint32_t f2tf32(float f) {
    uint32_t r;
    asm("cvt.rna.tf32.f32 %0, %1;" : "=r"(r) : "f"(f));
    return r;
}

__device__ __forceinline__ void mma_tf32(float d[4],
                                         uint32_t a0, uint32_t a1,
                                         uint32_t a2, uint32_t a3,
                                         uint32_t b0, uint32_t b1)
{
    asm("mma.sync.aligned.m16n8k8.row.col.f32.tf32.tf32.f32 "
        "{%0,%1,%2,%3}, {%4,%5,%6,%7}, {%8,%9}, {%0,%1,%2,%3};"
        : "+f"(d[0]), "+f"(d[1]), "+f"(d[2]), "+f"(d[3])
        : "r"(a0), "r"(a1), "r"(a2), "r"(a3), "r"(b0), "r"(b1));
}

__global__ __launch_bounds__(256)
void si_gemm_tc_kernel(const float* __restrict__ hidden,
                       const float* __restrict__ wsrc,
                       float*       __restrict__ out)
{
    extern __shared__ uint32_t smem_u[];
    uint32_t* s_w = smem_u;                              // [ITILE*WSTRIDE] tf32
    float*    s_h = (float*)(smem_u + ITILE * WSTRIDE);  // [2*KCHUNK*HSTRIDE] f32
    const uint32_t sh_base = (uint32_t)__cvta_generic_to_shared(s_h);

    const int tid  = threadIdx.x;
    const int lane = tid & 31;
    const int warp = tid >> 5;
    const int it   = blockIdx.x >> 3;                // 0..31
    const int js   = blockIdx.x & 7;                 // 0..7
    const int i0   = it * ITILE;
    const int jb   = js * 128;

    // ---- issue H chunk 0 via cp.async (buffer 0) ----
    {
        #pragma unroll
        for (int t = 0; t < 8; t++) {
            const int idx4 = tid + t * 256;          // 0..2047 f4
            const int k    = idx4 >> 5;              // 32 f4 per row
            const int m4   = idx4 & 31;
            cp16(sh_base + (k * HSTRIDE + m4 * 4) * 4,
                 &hidden[(size_t)(jb + k) * MDIM + m4 * 4]);
        }
        asm volatile("cp.async.commit_group;" ::: "memory");
    }

    // ---- stage W tile (32 x 128) tf32 (overlaps chunk-0 latency) ----
    #pragma unroll
    for (int t = 0; t < 4; t++) {
        const int idx4 = tid + t * 256;              // 0..1023 f4
        const int r    = idx4 >> 5;                  // 32 f4 per row
        const int c4   = idx4 & 31;
        const float4 v = *reinterpret_cast<const float4*>(
            &wsrc[(size_t)(i0 + r) * P + jb + c4 * 4]);
        uint4 u;
        u.x = f2tf32(v.x); u.y = f2tf32(v.y);
        u.z = f2tf32(v.z); u.w = f2tf32(v.w);
        *reinterpret_cast<uint4*>(&s_w[r * WSTRIDE + c4 * 4]) = u;
    }

    const int g  = lane >> 2;
    const int tg = lane & 3;
    const int mh = warp >> 2;
    const int nb = (warp & 3) * 32;

    float d[4][4];
    #pragma unroll
    for (int nt = 0; nt < 4; nt++)
        #pragma unroll
        for (int c = 0; c < 4; c++) d[nt][c] = 0.0f;

    #pragma unroll 1
    for (int kci = 0; kci < NCHUNKS; kci++) {
        if (kci + 1 < NCHUNKS) {
            const int kc1 = (kci + 1) * KCHUNK;
            const uint32_t bofs = ((kci + 1) & 1) * (KCHUNK * HSTRIDE) * 4;
            #pragma unroll
            for (int t = 0; t < 8; t++) {
                const int idx4 = tid + t * 256;
                const int k    = idx4 >> 5;
                const int m4   = idx4 & 31;
                cp16(sh_base + bofs + (k * HSTRIDE + m4 * 4) * 4,
                     &hidden[(size_t)(jb + kc1 + k) * MDIM + m4 * 4]);
            }
            asm volatile("cp.async.commit_group;" ::: "memory");
            asm volatile("cp.async.wait_group 1;" ::: "memory");
        } else {
            asm volatile("cp.async.wait_group 0;" ::: "memory");
        }
        __syncthreads();

        const float* sh = s_h + (kci & 1) * (KCHUNK * HSTRIDE);

        #pragma unroll
        for (int ks = 0; ks < 8; ks++) {
            const int kA = kci * KCHUNK + ks * 8;
            const int rowA = mh * 16 + g;
            const uint32_t a0 = s_w[(rowA    ) * WSTRIDE + kA + tg    ];
            const uint32_t a1 = s_w[(rowA + 8) * WSTRIDE + kA + tg    ];
            const uint32_t a2 = s_w[(rowA    ) * WSTRIDE + kA + tg + 4];
            const uint32_t a3 = s_w[(rowA + 8) * WSTRIDE + kA + tg + 4];

            const int kH = ks * 8;
            #pragma unroll
            for (int nt = 0; nt < 4; nt++) {
                const int n = nb + nt * 8 + g;
                const uint32_t b0 = f2tf32(sh[(kH + tg    ) * HSTRIDE + n]);
                const uint32_t b1 = f2tf32(sh[(kH + tg + 4) * HSTRIDE + n]);
                mma_tf32(d[nt], a0, a1, a2, a3, b0, b1);
            }
        }
        __syncthreads();
    }

    // ---- reduce directly into out via RED (out pre-zeroed by A) ----
    {
        const int r0 = i0 + mh * 16 + g;
        #pragma unroll
        for (int nt = 0; nt < 4; nt++) {
            const int col = nb + nt * 8 + 2 * tg;
            float* p0 = &out[(size_t)(r0    ) * MDIM + col];
            float* p1 = &out[(size_t)(r0 + 8) * MDIM + col];
            atomicAdd(p0,     d[nt][0]);
            atomicAdd(p0 + 1, d[nt][1]);
            atomicAdd(p1,     d[nt][2]);
            atomicAdd(p1 + 1, d[nt][3]);
        }
    }
}

extern "C" void kernel_launch(void* const* d_in, const int* in_sizes, int n_in,
                              void* d_out, int out_size)
{
    (void)in_sizes; (void)n_in; (void)out_size;
    const float* hidden = (const float*)d_in[0];   // [1024,128]
    const float* rela   = (const float*)d_in[1];   // [1024,1024,128]
    // d_in[2] = corr_index : unused
    const int*   nei    = (const int*)  d_in[3];   // [1024,1024]
    const float* att_w  = (const float*)d_in[4];   // [128]
    const float* att_b  = (const float*)d_in[5];   // [1]
    float* out = (float*)d_out;                    // [1024,128] f32

    float* wbuf;  cudaGetSymbolAddress((void**)&wbuf, g_wbuf);

    cudaFuncSetAttribute(si_row_kernel,
                         cudaFuncAttributeMaxDynamicSharedMemorySize, A_SMEM_BYTES);
    cudaFuncSetAttribute(si_gemm_tc_kernel,
                         cudaFuncAttributeMaxDynamicSharedMemorySize, B_SMEM);

    si_row_kernel<<<P, 256, A_SMEM_BYTES>>>(rela, nei, att_w, att_b, wbuf, out);
    si_gemm_tc_kernel<<<NTILES * JSPLIT, 256, B_SMEM>>>(hidden, wbuf, out);
}